// round 11
// baseline (speedup 1.0000x reference)
#include <cuda_runtime.h>
#include <cuda_fp16.h>
#include <cstdint>
#include <math.h>

#define BB 8
#define NN 2048
#define DD 128
#define KK 64
#define TT 32
#define TILES 64   // NN / TT

// per-tile partials (fully rewritten every launch -> no zero kernel)
__device__ float g_Pp[BB * TILES * KK * DD];   // 16 MB (L2-resident)
__device__ float g_sp[BB * TILES * KK];
__device__ unsigned int g_arr[BB];
__device__ unsigned int g_dep[BB];

// half strides: Cs/xs rows = 136 halves; At rows = 40 halves
#define STRC 136
#define STRA 40

// smem byte offsets
#define O_CS   0                       // 64*136*2 = 17408
#define O_XS   17408                   // 32*136*2 = 8704
#define O_AT   26112                   // 64*40*2  = 5120
#define O_CN2  31232                   // 64 floats
#define O_SSM  31488                   // 64 floats
#define O_RED  31744                   // 16 floats
#define SMEMB  31808

// ---- FFMA-only transcendentals (avoid the 0.5 op/cyc/SM MUFU pipe) ----
__device__ __forceinline__ float fexp(float x) {      // e^x, |x| small here
    float y = x * 1.4426950408889634f;
    float t = y + 12582912.f;                          // round-to-nearest int
    int j = __float_as_int(t) << 23;
    float f = y - (t - 12582912.f);                    // frac in [-0.5, 0.5]
    float p = 1.3333558e-3f;
    p = fmaf(p, f, 9.6181291e-3f);
    p = fmaf(p, f, 5.5504109e-2f);
    p = fmaf(p, f, 2.4022648e-1f);
    p = fmaf(p, f, 6.9314718e-1f);
    p = fmaf(p, f, 1.0f);
    return __int_as_float(__float_as_int(p) + j);
}
__device__ __forceinline__ float frsqrt(float s) {    // 1/sqrt(s), s > 0
    float h = __int_as_float(0x5f375a86 - (__float_as_int(s) >> 1));
    h = h * fmaf(-0.5f * s, h * h, 1.5f);
    h = h * fmaf(-0.5f * s, h * h, 1.5f);
    return h;
}
__device__ __forceinline__ float frcp(float s) {      // 1/s, s > 0
    float r = __int_as_float(0x7ef311c3 - __float_as_int(s));
    r = r * fmaf(-s, r, 2.0f);
    r = r * fmaf(-s, r, 2.0f);
    return r;
}

__device__ __forceinline__ void mma16(float* d, const uint32_t* a, const uint32_t* b) {
    asm volatile(
        "mma.sync.aligned.m16n8k16.row.col.f32.f16.f16.f32 "
        "{%0,%1,%2,%3}, {%4,%5,%6,%7}, {%8,%9}, {%0,%1,%2,%3};"
        : "+f"(d[0]), "+f"(d[1]), "+f"(d[2]), "+f"(d[3])
        : "r"(a[0]), "r"(a[1]), "r"(a[2]), "r"(a[3]), "r"(b[0]), "r"(b[1]));
}

// ---------------------------------------------------------------------------
// Fused kernel: grid = (64 tiles, 8 b) = 512 CTAs, 128 threads, 4 CTAs/SM max
// (all co-resident -> spin barrier is deadlock-free).
// Phase 1 (32-row tile): normalize -> fp16 smem, GEMM1 (m16n8k16), softmax
// (no max shift: args bounded by ||c||~0.08), GEMM2 -> fp32 partials.
// Phase 2: warp-split float4 reduction of k=tile over 64 tiles, finalize.
// ---------------------------------------------------------------------------
__global__ void __launch_bounds__(128, 4)
nv_main(const float* __restrict__ x, const float* __restrict__ cent,
        float* __restrict__ out) {
    extern __shared__ char smc[];
    half*  Cs  = (half*)(smc + O_CS);
    half*  xs  = (half*)(smc + O_XS);
    half*  At  = (half*)(smc + O_AT);
    float* cn2 = (float*)(smc + O_CN2);
    float* ssm = (float*)(smc + O_SSM);
    float* red = (float*)(smc + O_RED);

    const int tid = threadIdx.x, w = tid >> 5, l = tid & 31;
    const int g = l >> 2, t = l & 3;           // mma groupID / thread-in-group
    const int b = blockIdx.y, tile = blockIdx.x;
    const int nb = w * 8;

    if (tid < 64) ssm[tid] = 0.f;

    // ---- phase A: x rows -> regs; C -> fp16 smem; normalize x -> fp16 smem ----
    {
        const float4* x4 = (const float4*)(x + ((size_t)b * NN + (size_t)tile * TT) * DD);
        float4 xv[8];
        #pragma unroll
        for (int i = 0; i < 8; i++) xv[i] = x4[(w * 8 + i) * 32 + l];

        const float4* c4 = (const float4*)cent;
        #pragma unroll
        for (int i = tid; i < KK * DD / 4; i += 128) {
            float4 v = c4[i];
            int k = i >> 5, d4 = (i & 31) * 4;
            *(half2*)&Cs[k * STRC + d4]     = __floats2half2_rn(v.x, v.y);
            *(half2*)&Cs[k * STRC + d4 + 2] = __floats2half2_rn(v.z, v.w);
        }

        #pragma unroll
        for (int i = 0; i < 8; i++) {
            float4 v = xv[i];
            float ss = v.x * v.x + v.y * v.y + v.z * v.z + v.w * v.w;
            #pragma unroll
            for (int o = 16; o; o >>= 1) ss += __shfl_xor_sync(~0u, ss, o);
            float ri = frsqrt(fmaxf(ss, 1e-24f));
            int r = w * 8 + i;
            *(half2*)&xs[r * STRC + 4 * l]     = __floats2half2_rn(v.x * ri, v.y * ri);
            *(half2*)&xs[r * STRC + 4 * l + 2] = __floats2half2_rn(v.z * ri, v.w * ri);
        }
    }
    __syncthreads();

    // ---- cn2[k] = ||c_k||^2 (from rounded halves, consistent with MMA) ----
    {
        int kc = tid >> 1, q = tid & 1;
        float s = 0.f;
        #pragma unroll
        for (int j = 0; j < 32; j++) {
            float2 f = __half22float2(*(const half2*)&Cs[kc * STRC + q * 64 + 2 * j]);
            s += f.x * f.x + f.y * f.y;
        }
        s += __shfl_xor_sync(~0u, s, 1);
        if (q == 0) cn2[kc] = s;
    }
    __syncthreads();

    // ---- GEMM1: S^T[k][n] = C[k][d] * xn[n][d]^T ; warp w: n in [8w,8w+8) ----
    const uint32_t* Cw = (const uint32_t*)Cs;
    const uint32_t* Xw = (const uint32_t*)xs;
    float acc[4][4];
    #pragma unroll
    for (int mt = 0; mt < 4; mt++)
        #pragma unroll
        for (int q = 0; q < 4; q++) acc[mt][q] = 0.f;

    #pragma unroll
    for (int s = 0; s < 8; s++) {
        const int cw = 8 * s + t;
        uint32_t a[4][4], bf[2];
        #pragma unroll
        for (int mt = 0; mt < 4; mt++) {
            int base = (mt * 16 + g) * 68 + cw;
            a[mt][0] = Cw[base];
            a[mt][1] = Cw[base + 8 * 68];
            a[mt][2] = Cw[base + 4];
            a[mt][3] = Cw[base + 8 * 68 + 4];
        }
        int bb2 = (nb + g) * 68 + cw;
        bf[0] = Xw[bb2];
        bf[1] = Xw[bb2 + 4];
        #pragma unroll
        for (int mt = 0; mt < 4; mt++) mma16(acc[mt], a[mt], bf);
    }

    // ---- softmax per n-column over k=64 (warp-local, NO max shift) ----
    // dist = cn2[k] - 2*S; args bounded in [-0.15, 0.15] -> exp directly.
    float s0 = 0.f, s1 = 0.f;
    #pragma unroll
    for (int mt = 0; mt < 4; mt++) {
        float cA = cn2[mt * 16 + g], cB = cn2[mt * 16 + g + 8];
        acc[mt][0] = fexp(fmaf(-2.f, acc[mt][0], cA));
        acc[mt][1] = fexp(fmaf(-2.f, acc[mt][1], cA));
        acc[mt][2] = fexp(fmaf(-2.f, acc[mt][2], cB));
        acc[mt][3] = fexp(fmaf(-2.f, acc[mt][3], cB));
        s0 += acc[mt][0] + acc[mt][2];
        s1 += acc[mt][1] + acc[mt][3];
    }
    #pragma unroll
    for (int o = 4; o <= 16; o <<= 1) {
        s0 += __shfl_xor_sync(~0u, s0, o);
        s1 += __shfl_xor_sync(~0u, s1, o);
    }
    s0 = frcp(s0);
    s1 = frcp(s1);

    // assign -> At[k][n] (fp16) + row sums -> ssm
    #pragma unroll
    for (int mt = 0; mt < 4; mt++) {
        float a0 = acc[mt][0] * s0, a1 = acc[mt][1] * s1;
        float a2 = acc[mt][2] * s0, a3 = acc[mt][3] * s1;
        float rs0 = a0 + a1, rs1 = a2 + a3;
        int rr = mt * 16 + g;
        *(half2*)&At[rr * STRA + nb + 2 * t]       = __floats2half2_rn(a0, a1);
        *(half2*)&At[(rr + 8) * STRA + nb + 2 * t] = __floats2half2_rn(a2, a3);
        rs0 += __shfl_xor_sync(~0u, rs0, 1);
        rs0 += __shfl_xor_sync(~0u, rs0, 2);
        rs1 += __shfl_xor_sync(~0u, rs1, 1);
        rs1 += __shfl_xor_sync(~0u, rs1, 2);
        if (t == 0) {
            atomicAdd(&ssm[rr], rs0);
            atomicAdd(&ssm[rr + 8], rs1);
        }
    }
    __syncthreads();

    // ---- GEMM2: P[k][d] = At[k][n] * Xn[n][d] ; warp w: d in [32w,32w+32) ----
    const uint32_t* Aw = (const uint32_t*)At;
    const unsigned short* Xu = (const unsigned short*)xs;
    const int db = 32 * w;
    float pc[4][4][4];
    #pragma unroll
    for (int mt = 0; mt < 4; mt++)
        #pragma unroll
        for (int nt = 0; nt < 4; nt++)
            #pragma unroll
            for (int q = 0; q < 4; q++) pc[mt][nt][q] = 0.f;

    #pragma unroll
    for (int s = 0; s < 2; s++) {
        uint32_t a[4][4];
        #pragma unroll
        for (int mt = 0; mt < 4; mt++) {
            int base = (mt * 16 + g) * 20 + 8 * s + t;
            a[mt][0] = Aw[base];
            a[mt][1] = Aw[base + 160];
            a[mt][2] = Aw[base + 4];
            a[mt][3] = Aw[base + 164];
        }
        #pragma unroll
        for (int nt = 0; nt < 4; nt++) {
            int dcol = db + 8 * nt + g;
            int rh = (16 * s + 2 * t) * STRC + dcol;
            uint32_t lo0 = Xu[rh],            hi0 = Xu[rh + STRC];
            uint32_t lo1 = Xu[rh + 8 * STRC], hi1 = Xu[rh + 9 * STRC];
            uint32_t bfr[2] = { lo0 | (hi0 << 16), lo1 | (hi1 << 16) };
            #pragma unroll
            for (int mt = 0; mt < 4; mt++) mma16(pc[mt][nt], a[mt], bfr);
        }
    }

    // store per-tile partials
    float* Pb = g_Pp + (size_t)(b * TILES + tile) * KK * DD;
    #pragma unroll
    for (int mt = 0; mt < 4; mt++)
        #pragma unroll
        for (int nt = 0; nt < 4; nt++) {
            int rr = mt * 16 + g, dd2 = db + 8 * nt + 2 * t;
            *(float2*)&Pb[rr * DD + dd2]       = make_float2(pc[mt][nt][0], pc[mt][nt][1]);
            *(float2*)&Pb[(rr + 8) * DD + dd2] = make_float2(pc[mt][nt][2], pc[mt][nt][3]);
        }
    if (tid < 64) g_sp[(b * TILES + tile) * KK + tid] = ssm[tid];

    // ================= cross-CTA barrier (per b, 64 arrivals) =================
    __threadfence();
    __syncthreads();
    if (tid == 0) {
        atomicAdd(&g_arr[b], 1u);
        volatile unsigned int* va = &g_arr[b];
        while (*va < TILES) __nanosleep(64);
        __threadfence();
        unsigned int my = atomicAdd(&g_dep[b], 1u);
        if (my == TILES - 1) { g_arr[b] = 0u; g_dep[b] = 0u; }
    }
    __syncthreads();

    // ================= phase 2: CTA (b,tile) finalizes k = tile =================
    // Warp w reduces tiles [16w,16w+16) with float4 loads (MLP-16), stages in
    // smem (reusing the Cs region), then 128 threads combine + epilogue.
    {
        const int k = tile;
        float* ps = (float*)smc;   // 4 warps x 128 floats = 2KB (Cs is dead)
        const float4* P4 = (const float4*)g_Pp;
        float4 a = make_float4(0.f, 0.f, 0.f, 0.f);
        #pragma unroll
        for (int tt = w * 16; tt < w * 16 + 16; tt++) {
            float4 v = __ldcg(&P4[((size_t)(b * TILES + tt) * KK + k) * 32 + l]);
            a.x += v.x; a.y += v.y; a.z += v.z; a.w += v.w;
        }
        ((float4*)(ps + w * 128))[l] = a;

        float sv = 0.f;
        if (tid < 64) sv = __ldcg(&g_sp[(b * TILES + tid) * KK + k]);
        #pragma unroll
        for (int o = 16; o; o >>= 1) sv += __shfl_xor_sync(~0u, sv, o);
        if (l == 0 && w < 2) red[w] = sv;
        __syncthreads();

        const int d = tid;
        float v = (ps[d] + ps[128 + d]) + (ps[256 + d] + ps[384 + d]);
        float sk = red[0] + red[1];
        v = fmaf(-sk, cent[k * DD + d], v);
        float ssq = v * v;
        #pragma unroll
        for (int o = 16; o; o >>= 1) ssq += __shfl_xor_sync(~0u, ssq, o);
        if (l == 0) red[4 + w] = ssq;
        __syncthreads();
        float tot = (red[4] + red[5]) + (red[6] + red[7]);
        float sc = 0.125f * frsqrt(fmaxf(tot, 1e-24f));   // exact global norm = 8
        out[((size_t)b * KK + k) * DD + d] = v * sc;
    }
}

// ---------------------------------------------------------------------------
extern "C" void kernel_launch(void* const* d_in, const int* in_sizes, int n_in,
                              void* d_out, int out_size) {
    (void)in_sizes; (void)n_in; (void)out_size;
    const float* x    = (const float*)d_in[0];
    const float* cent = (const float*)d_in[1];
    float* out        = (float*)d_out;

    cudaFuncSetAttribute(nv_main, cudaFuncAttributeMaxDynamicSharedMemorySize, SMEMB);
    nv_main<<<dim3(TILES, BB), 128, SMEMB>>>(x, cent, out);
}

// round 12
// speedup vs baseline: 1.0171x; 1.0171x over previous
#include <cuda_runtime.h>
#include <cuda_fp16.h>
#include <cstdint>
#include <math.h>

#define BB 8
#define NN 2048
#define DD 128
#define KK 64
#define TT 32
#define TILES 64   // NN / TT

// per-tile partials (fully rewritten every launch -> no zero kernel)
__device__ float g_Pp[BB * TILES * KK * DD];   // 16 MB (L2-resident)
__device__ float g_sp[BB * TILES * KK];
__device__ unsigned int g_arr[BB];
__device__ unsigned int g_dep[BB];
__device__ half  g_Ch[KK * DD];                // fp16 centroids (prep kernel)
__device__ float g_cn2[KK];                    // ||c_k||^2 from rounded halves

// half strides: Cs/xs rows = 136 halves; At rows = 40 halves
#define STRC 136
#define STRA 40

// smem byte offsets
#define O_CS   0                       // 64*136*2 = 17408
#define O_XS   17408                   // 32*136*2 = 8704
#define O_AT   26112                   // 64*40*2  = 5120
#define O_CN2  31232                   // 64 floats
#define O_SSM  31488                   // 64 floats
#define O_RED  31744                   // 16 floats
#define SMEMB  31808

// ---- FFMA-only transcendentals (avoid the 0.5 op/cyc/SM MUFU pipe) ----
__device__ __forceinline__ float fexp(float x) {      // e^x, |x| small here
    float y = x * 1.4426950408889634f;
    float t = y + 12582912.f;                          // round-to-nearest int
    int j = __float_as_int(t) << 23;
    float f = y - (t - 12582912.f);                    // frac in [-0.5, 0.5]
    float p = 1.3333558e-3f;
    p = fmaf(p, f, 9.6181291e-3f);
    p = fmaf(p, f, 5.5504109e-2f);
    p = fmaf(p, f, 2.4022648e-1f);
    p = fmaf(p, f, 6.9314718e-1f);
    p = fmaf(p, f, 1.0f);
    return __int_as_float(__float_as_int(p) + j);
}
__device__ __forceinline__ float frsqrt(float s) {    // 1/sqrt(s), s > 0
    float h = __int_as_float(0x5f375a86 - (__float_as_int(s) >> 1));
    h = h * fmaf(-0.5f * s, h * h, 1.5f);
    h = h * fmaf(-0.5f * s, h * h, 1.5f);
    return h;
}
__device__ __forceinline__ float frcp(float s) {      // 1/s, s > 0
    float r = __int_as_float(0x7ef311c3 - __float_as_int(s));
    r = r * fmaf(-s, r, 2.0f);
    r = r * fmaf(-s, r, 2.0f);
    return r;
}

__device__ __forceinline__ void mma16(float* d, const uint32_t* a, const uint32_t* b) {
    asm volatile(
        "mma.sync.aligned.m16n8k16.row.col.f32.f16.f16.f32 "
        "{%0,%1,%2,%3}, {%4,%5,%6,%7}, {%8,%9}, {%0,%1,%2,%3};"
        : "+f"(d[0]), "+f"(d[1]), "+f"(d[2]), "+f"(d[3])
        : "r"(a[0]), "r"(a[1]), "r"(a[2]), "r"(a[3]), "r"(b[0]), "r"(b[1]));
}
#define LDSM4(r, addr) \
    asm volatile("ldmatrix.sync.aligned.m8n8.x4.shared.b16 {%0,%1,%2,%3}, [%4];" \
        : "=r"((r)[0]), "=r"((r)[1]), "=r"((r)[2]), "=r"((r)[3]) : "r"(addr))

// ---------------------------------------------------------------------------
// prep: convert C to fp16 + cn2 from rounded halves. 1 block, 256 threads.
// ---------------------------------------------------------------------------
__global__ void __launch_bounds__(256, 1)
nv_prep(const float* __restrict__ cent) {
    const int w = threadIdx.x >> 5, l = threadIdx.x & 31;
    #pragma unroll
    for (int k = w; k < KK; k += 8) {
        float4 v = ((const float4*)cent)[k * 32 + l];
        half2 h01 = __floats2half2_rn(v.x, v.y);
        half2 h23 = __floats2half2_rn(v.z, v.w);
        uint2 u;
        u.x = *(uint32_t*)&h01;
        u.y = *(uint32_t*)&h23;
        *(uint2*)&g_Ch[k * DD + 4 * l] = u;
        float2 f01 = __half22float2(h01), f23 = __half22float2(h23);
        float s = f01.x * f01.x + f01.y * f01.y + f23.x * f23.x + f23.y * f23.y;
        #pragma unroll
        for (int o = 16; o; o >>= 1) s += __shfl_xor_sync(~0u, s, o);
        if (l == 0) g_cn2[k] = s;
    }
}

// ---------------------------------------------------------------------------
// Fused kernel: grid = (64 tiles, 8 b) = 512 CTAs, 128 threads, 4 CTAs/SM max
// (all co-resident -> spin barrier is deadlock-free).
// ---------------------------------------------------------------------------
__global__ void __launch_bounds__(128, 4)
nv_main(const float* __restrict__ x, const float* __restrict__ cent,
        float* __restrict__ out) {
    extern __shared__ char smc[];
    half*  Cs  = (half*)(smc + O_CS);
    half*  xs  = (half*)(smc + O_XS);
    half*  At  = (half*)(smc + O_AT);
    float* cn2 = (float*)(smc + O_CN2);
    float* ssm = (float*)(smc + O_SSM);
    float* red = (float*)(smc + O_RED);
    const uint32_t sb = (uint32_t)__cvta_generic_to_shared(smc);

    const int tid = threadIdx.x, w = tid >> 5, l = tid & 31;
    const int g = l >> 2, t = l & 3;           // mma groupID / thread-in-group
    const int b = blockIdx.y, tile = blockIdx.x;
    const int nb = w * 8;

    if (tid < 64) {
        ssm[tid] = 0.f;
        cn2[tid] = g_cn2[tid];
    }

    // ---- phase A: copy fp16 C -> smem; load x rows, normalize -> fp16 smem ----
    {
        const float4* x4 = (const float4*)(x + ((size_t)b * NN + (size_t)tile * TT) * DD);
        float4 xv[8];
        #pragma unroll
        for (int i = 0; i < 8; i++) xv[i] = x4[(w * 8 + i) * 32 + l];

        const uint4* Cg = (const uint4*)g_Ch;
        #pragma unroll
        for (int i = tid; i < KK * DD / 8; i += 128) {   // 256 uint4s
            uint4 v = Cg[i];
            int k = i >> 4, off = (i & 15) * 8;
            *(uint4*)&Cs[k * STRC + off] = v;
        }

        #pragma unroll
        for (int i = 0; i < 8; i++) {
            float4 v = xv[i];
            float ss = v.x * v.x + v.y * v.y + v.z * v.z + v.w * v.w;
            #pragma unroll
            for (int o = 16; o; o >>= 1) ss += __shfl_xor_sync(~0u, ss, o);
            float ri = frsqrt(fmaxf(ss, 1e-24f));
            int r = w * 8 + i;
            *(half2*)&xs[r * STRC + 4 * l]     = __floats2half2_rn(v.x * ri, v.y * ri);
            *(half2*)&xs[r * STRC + 4 * l + 2] = __floats2half2_rn(v.z * ri, v.w * ri);
        }
    }
    __syncthreads();

    // ---- GEMM1: S^T[k][n] = C[k][d] * xn[n][d]^T ; warp w: n in [8w,8w+8) ----
    // A-fragments via ldmatrix.x4 (lane row = l&15, +8 halves for lanes>=16)
    const uint32_t* Xw = (const uint32_t*)xs;
    const uint32_t aAddr1 = sb + O_CS + (uint32_t)((l & 15) * 272 + (l >> 4) * 16);
    float acc[4][4];
    #pragma unroll
    for (int mt = 0; mt < 4; mt++)
        #pragma unroll
        for (int q = 0; q < 4; q++) acc[mt][q] = 0.f;

    #pragma unroll
    for (int s = 0; s < 8; s++) {
        uint32_t a[4][4], bf[2];
        #pragma unroll
        for (int mt = 0; mt < 4; mt++)
            LDSM4(a[mt], aAddr1 + mt * 4352 + s * 32);
        int bb2 = (nb + g) * 68 + 8 * s + t;
        bf[0] = Xw[bb2];
        bf[1] = Xw[bb2 + 4];
        #pragma unroll
        for (int mt = 0; mt < 4; mt++) mma16(acc[mt], a[mt], bf);
    }

    // ---- softmax per n-column over k=64 (warp-local, no max shift needed) ----
    float s0 = 0.f, s1 = 0.f;
    #pragma unroll
    for (int mt = 0; mt < 4; mt++) {
        float cA = cn2[mt * 16 + g], cB = cn2[mt * 16 + g + 8];
        acc[mt][0] = fexp(fmaf(-2.f, acc[mt][0], cA));
        acc[mt][1] = fexp(fmaf(-2.f, acc[mt][1], cA));
        acc[mt][2] = fexp(fmaf(-2.f, acc[mt][2], cB));
        acc[mt][3] = fexp(fmaf(-2.f, acc[mt][3], cB));
        s0 += acc[mt][0] + acc[mt][2];
        s1 += acc[mt][1] + acc[mt][3];
    }
    #pragma unroll
    for (int o = 4; o <= 16; o <<= 1) {
        s0 += __shfl_xor_sync(~0u, s0, o);
        s1 += __shfl_xor_sync(~0u, s1, o);
    }
    s0 = frcp(s0);
    s1 = frcp(s1);

    // assign -> At[k][n] (fp16) + row sums -> ssm
    #pragma unroll
    for (int mt = 0; mt < 4; mt++) {
        float a0 = acc[mt][0] * s0, a1 = acc[mt][1] * s1;
        float a2 = acc[mt][2] * s0, a3 = acc[mt][3] * s1;
        float rs0 = a0 + a1, rs1 = a2 + a3;
        int rr = mt * 16 + g;
        *(half2*)&At[rr * STRA + nb + 2 * t]       = __floats2half2_rn(a0, a1);
        *(half2*)&At[(rr + 8) * STRA + nb + 2 * t] = __floats2half2_rn(a2, a3);
        rs0 += __shfl_xor_sync(~0u, rs0, 1);
        rs0 += __shfl_xor_sync(~0u, rs0, 2);
        rs1 += __shfl_xor_sync(~0u, rs1, 1);
        rs1 += __shfl_xor_sync(~0u, rs1, 2);
        if (t == 0) {
            atomicAdd(&ssm[rr], rs0);
            atomicAdd(&ssm[rr + 8], rs1);
        }
    }
    __syncthreads();

    // ---- GEMM2: P[k][d] = At[k][n] * Xn[n][d] ; warp w: d in [32w,32w+32) ----
    const unsigned short* Xu = (const unsigned short*)xs;
    const uint32_t aAddr2 = sb + O_AT + (uint32_t)((l & 15) * 80 + (l >> 4) * 16);
    const int db = 32 * w;
    float pc[4][4][4];
    #pragma unroll
    for (int mt = 0; mt < 4; mt++)
        #pragma unroll
        for (int nt = 0; nt < 4; nt++)
            #pragma unroll
            for (int q = 0; q < 4; q++) pc[mt][nt][q] = 0.f;

    #pragma unroll
    for (int s = 0; s < 2; s++) {
        uint32_t a[4][4];
        #pragma unroll
        for (int mt = 0; mt < 4; mt++)
            LDSM4(a[mt], aAddr2 + mt * 1280 + s * 32);
        #pragma unroll
        for (int nt = 0; nt < 4; nt++) {
            int dcol = db + 8 * nt + g;
            int rh = (16 * s + 2 * t) * STRC + dcol;
            uint32_t lo0 = Xu[rh],            hi0 = Xu[rh + STRC];
            uint32_t lo1 = Xu[rh + 8 * STRC], hi1 = Xu[rh + 9 * STRC];
            uint32_t bfr[2] = { lo0 | (hi0 << 16), lo1 | (hi1 << 16) };
            #pragma unroll
            for (int mt = 0; mt < 4; mt++) mma16(pc[mt][nt], a[mt], bfr);
        }
    }

    // store per-tile partials
    float* Pb = g_Pp + (size_t)(b * TILES + tile) * KK * DD;
    #pragma unroll
    for (int mt = 0; mt < 4; mt++)
        #pragma unroll
        for (int nt = 0; nt < 4; nt++) {
            int rr = mt * 16 + g, dd2 = db + 8 * nt + 2 * t;
            *(float2*)&Pb[rr * DD + dd2]       = make_float2(pc[mt][nt][0], pc[mt][nt][1]);
            *(float2*)&Pb[(rr + 8) * DD + dd2] = make_float2(pc[mt][nt][2], pc[mt][nt][3]);
        }
    if (tid < 64) g_sp[(b * TILES + tile) * KK + tid] = ssm[tid];

    // ================= cross-CTA barrier (per b, 64 arrivals) =================
    __threadfence();
    __syncthreads();
    if (tid == 0) {
        atomicAdd(&g_arr[b], 1u);
        volatile unsigned int* va = &g_arr[b];
        while (*va < TILES) __nanosleep(64);
        __threadfence();
        unsigned int my = atomicAdd(&g_dep[b], 1u);
        if (my == TILES - 1) { g_arr[b] = 0u; g_dep[b] = 0u; }
    }
    __syncthreads();

    // ================= phase 2: CTA (b,tile) finalizes k = tile =================
    {
        const int k = tile;
        float* ps = (float*)smc;   // reuse Cs region (dead)
        const float4* P4 = (const float4*)g_Pp;
        float4 a = make_float4(0.f, 0.f, 0.f, 0.f);
        #pragma unroll
        for (int tt = w * 16; tt < w * 16 + 16; tt++) {
            float4 v = __ldcg(&P4[((size_t)(b * TILES + tt) * KK + k) * 32 + l]);
            a.x += v.x; a.y += v.y; a.z += v.z; a.w += v.w;
        }
        ((float4*)(ps + w * 128))[l] = a;

        float sv = 0.f;
        if (tid < 64) sv = __ldcg(&g_sp[(b * TILES + tid) * KK + k]);
        #pragma unroll
        for (int o = 16; o; o >>= 1) sv += __shfl_xor_sync(~0u, sv, o);
        if (l == 0 && w < 2) red[w] = sv;
        __syncthreads();

        const int d = tid;
        float v = (ps[d] + ps[128 + d]) + (ps[256 + d] + ps[384 + d]);
        float sk = red[0] + red[1];
        v = fmaf(-sk, cent[k * DD + d], v);
        float ssq = v * v;
        #pragma unroll
        for (int o = 16; o; o >>= 1) ssq += __shfl_xor_sync(~0u, ssq, o);
        if (l == 0) red[4 + w] = ssq;
        __syncthreads();
        float tot = (red[4] + red[5]) + (red[6] + red[7]);
        float sc = 0.125f * frsqrt(fmaxf(tot, 1e-24f));   // exact global norm = 8
        out[((size_t)b * KK + k) * DD + d] = v * sc;
    }
}

// ---------------------------------------------------------------------------
extern "C" void kernel_launch(void* const* d_in, const int* in_sizes, int n_in,
                              void* d_out, int out_size) {
    (void)in_sizes; (void)n_in; (void)out_size;
    const float* x    = (const float*)d_in[0];
    const float* cent = (const float*)d_in[1];
    float* out        = (float*)d_out;

    cudaFuncSetAttribute(nv_main, cudaFuncAttributeMaxDynamicSharedMemorySize, SMEMB);
    nv_prep<<<1, 256>>>(cent);
    nv_main<<<dim3(TILES, BB), 128, SMEMB>>>(x, cent, out);
}